// round 11
// baseline (speedup 1.0000x reference)
#include <cuda_runtime.h>
#include <cuda_bf16.h>

// ZBL repulsion energy: per-pair 4-term exponential screening, scatter-add to atoms.
// Inputs (metadata order):
//  0: N (scalar)        1: Zf [N] f32      2: rij [P] f32      3: cutoff_values [P] f32
//  4: idx_i [P] i32     5: idx_j [P] i32   6: adiv [1]         7: apow [1]
//  8..11: c1..c4 [1]    12..15: a1..a4 [1]
// Output: f32 [N]
//
// Structural analysis (R1-R9): the kernel is pinned at the L1tex-wavefront /
// LSU-lane floor: 2 random gather lanes + 1 atomic lane per pair = 48M lane-ops.
// Cache policy, persistent grids, and MLP batching are all neutral-to-negative.
// This is the best-measured configuration (R4) with atomic/compute interleave.

#define NA_MAX 500000
#define PPT 4  // pairs per thread

// per-atom Z as uint8 (Z in [1,94]) -> 0.5MB table
__device__ unsigned char g_z8[NA_MAX];
// derived scalars: [0]=sp(adiv) [1..4]=KEHALF*c_norm [5..8]=-log2(e)*sp(a_k) [9]=sp(apow)
__device__ float g_par[12];

__device__ __forceinline__ float softplus_accurate(float x) {
    return log1pf(expf(x));
}

// Fused prep: u8 Z table + zero out + (thread 0) derived pair params. 4 atoms/thread.
__global__ void atoms_kernel(const float* __restrict__ Zf, float* __restrict__ out, int n,
                             const float* __restrict__ adiv, const float* __restrict__ apow,
                             const float* __restrict__ c1, const float* __restrict__ c2,
                             const float* __restrict__ c3, const float* __restrict__ c4,
                             const float* __restrict__ a1, const float* __restrict__ a2,
                             const float* __restrict__ a3, const float* __restrict__ a4) {
    int t = blockIdx.x * blockDim.x + threadIdx.x;
    if (t == 0) {
        const float KEHALF = 7.199822675975274f;
        const float NLOG2E = -1.4426950408889634f;
        float c1p = softplus_accurate(c1[0]);
        float c2p = softplus_accurate(c2[0]);
        float c3p = softplus_accurate(c3[0]);
        float c4p = softplus_accurate(c4[0]);
        float inv_csum = KEHALF / (c1p + c2p + c3p + c4p);
        g_par[0] = softplus_accurate(adiv[0]);
        g_par[1] = c1p * inv_csum;
        g_par[2] = c2p * inv_csum;
        g_par[3] = c3p * inv_csum;
        g_par[4] = c4p * inv_csum;
        g_par[5] = NLOG2E * softplus_accurate(a1[0]);
        g_par[6] = NLOG2E * softplus_accurate(a2[0]);
        g_par[7] = NLOG2E * softplus_accurate(a3[0]);
        g_par[8] = NLOG2E * softplus_accurate(a4[0]);
        g_par[9] = softplus_accurate(apow[0]);
    }
    int base = t * 4;
    if (base + 4 <= n) {
        float4 z4 = *reinterpret_cast<const float4*>(Zf + base);
        uchar4 u;
        u.x = (unsigned char)__float2int_rn(z4.x);
        u.y = (unsigned char)__float2int_rn(z4.y);
        u.z = (unsigned char)__float2int_rn(z4.z);
        u.w = (unsigned char)__float2int_rn(z4.w);
        *reinterpret_cast<uchar4*>(g_z8 + base) = u;
        *reinterpret_cast<float4*>(out + base) = make_float4(0.f, 0.f, 0.f, 0.f);
    } else {
        for (int i = base; i < n; i++) {
            g_z8[i] = (unsigned char)__float2int_rn(Zf[i]);
            out[i] = 0.0f;
        }
    }
}

__global__ void __launch_bounds__(256) pairs_kernel(
    const float* __restrict__ rij, const float* __restrict__ cv,
    const int* __restrict__ idx_i, const int* __restrict__ idx_j,
    float* __restrict__ out, int npairs) {
    long long base = (long long)(blockIdx.x * blockDim.x + threadIdx.x) * PPT;
    if (base >= npairs) return;

    const float spadiv = g_par[0];
    const float k1 = g_par[1], k2 = g_par[2], k3 = g_par[3], k4 = g_par[4];
    const float q1 = g_par[5], q2 = g_par[6], q3 = g_par[7], q4 = g_par[8];
    const float spapow = g_par[9];

    if (base + PPT <= npairs) {
        // streaming loads: evict-first so the 0.5MB atom table keeps L1 lines
        float4 r4 = __ldcs(reinterpret_cast<const float4*>(rij + base));
        float4 c4 = __ldcs(reinterpret_cast<const float4*>(cv + base));
        int4   i4 = __ldcs(reinterpret_cast<const int4*>(idx_i + base));
        int4   j4 = __ldcs(reinterpret_cast<const int4*>(idx_j + base));
        float r[PPT] = {r4.x, r4.y, r4.z, r4.w};
        float c[PPT] = {c4.x, c4.y, c4.z, c4.w};
        int ia[PPT] = {i4.x, i4.y, i4.z, i4.w};
        int ja[PPT] = {j4.x, j4.y, j4.z, j4.w};

        // issue all 8 u8 gathers up front (they are the long-latency critical path)
        unsigned char zbi[PPT], zbj[PPT];
#pragma unroll
        for (int k = 0; k < PPT; k++) zbi[k] = __ldg(&g_z8[ia[k]]);
#pragma unroll
        for (int k = 0; k < PPT; k++) zbj[k] = __ldg(&g_z8[ja[k]]);

        // interleave: atomic for pair k issues while pair k+1's MUFU chain runs,
        // overlapping LSU lane processing with compute instead of batching REDs
#pragma unroll
        for (int k = 0; k < PPT; k++) {
            float Zi = (float)zbi[k];
            float Zj = (float)zbj[k];
            float zi = exp2f(spapow * __log2f(Zi));  // z = Z^sp(apow)
            float zj = exp2f(spapow * __log2f(Zj));
            float u = (zi + zj) * spadiv * r[k];     // a * r
            float f = k1 * exp2f(q1 * u)
                    + k2 * exp2f(q2 * u)
                    + k3 * exp2f(q3 * u)
                    + k4 * exp2f(q4 * u);
            atomicAdd(&out[ia[k]], __fdividef(f * c[k] * Zi * Zj, r[k]));
        }
    } else {
        int cnt = (int)(npairs - base);
        for (int k = 0; k < cnt; k++) {
            float rk = rij[base + k];
            float ck = cv[base + k];
            int i = idx_i[base + k];
            int j = idx_j[base + k];
            float Zi = (float)g_z8[i];
            float Zj = (float)g_z8[j];
            float zi = exp2f(spapow * __log2f(Zi));
            float zj = exp2f(spapow * __log2f(Zj));
            float u = (zi + zj) * spadiv * rk;
            float f = k1 * exp2f(q1 * u)
                    + k2 * exp2f(q2 * u)
                    + k3 * exp2f(q3 * u)
                    + k4 * exp2f(q4 * u);
            atomicAdd(&out[i], __fdividef(f * ck * Zi * Zj, rk));
        }
    }
}

extern "C" void kernel_launch(void* const* d_in, const int* in_sizes, int n_in,
                              void* d_out, int out_size) {
    const float* Zf    = (const float*)d_in[1];
    const float* rij   = (const float*)d_in[2];
    const float* cvv   = (const float*)d_in[3];
    const int*   idx_i = (const int*)d_in[4];
    const int*   idx_j = (const int*)d_in[5];
    const float* adiv  = (const float*)d_in[6];
    const float* apow  = (const float*)d_in[7];
    const float* c1    = (const float*)d_in[8];
    const float* c2    = (const float*)d_in[9];
    const float* c3    = (const float*)d_in[10];
    const float* c4    = (const float*)d_in[11];
    const float* a1    = (const float*)d_in[12];
    const float* a2    = (const float*)d_in[13];
    const float* a3    = (const float*)d_in[14];
    const float* a4    = (const float*)d_in[15];

    int n = in_sizes[1];
    int p = in_sizes[2];
    float* out = (float*)d_out;

    int athreads = (n + 3) / 4;
    int ab = (athreads + 255) / 256;
    atoms_kernel<<<ab, 256>>>(Zf, out, n, adiv, apow, c1, c2, c3, c4, a1, a2, a3, a4);

    long long nthreads = ((long long)p + PPT - 1) / PPT;
    int pb = (int)((nthreads + 255) / 256);
    pairs_kernel<<<pb, 256>>>(rij, cvv, idx_i, idx_j, out, p);
}

// round 12
// speedup vs baseline: 1.0357x; 1.0357x over previous
#include <cuda_runtime.h>
#include <cuda_bf16.h>

// ZBL repulsion energy: per-pair 4-term exponential screening, scatter-add to atoms.
// Inputs (metadata order):
//  0: N (scalar)        1: Zf [N] f32      2: rij [P] f32      3: cutoff_values [P] f32
//  4: idx_i [P] i32     5: idx_j [P] i32   6: adiv [1]         7: apow [1]
//  8..11: c1..c4 [1]    12..15: a1..a4 [1]
// Output: f32 [N]
//
// Structural finding (R1-R10): pairs kernel is at the L1tex-wavefront / LSU-lane
// floor (2 random gather lanes + 1 atomic lane per pair = 48M lane-ops ~ 170us).
// This round: best-measured pairs config (R4) + leaner atoms prologue.

#define NA_MAX 500000
#define PPT 4  // pairs per thread

// per-atom Z as uint8 (Z in [1,94]) -> 0.5MB table
__device__ unsigned char g_z8[NA_MAX];
// derived scalars: [0]=sp(adiv) [1..4]=KEHALF*c_norm [5..8]=-log2(e)*sp(a_k) [9]=sp(apow)
__device__ float g_par[12];

__device__ __forceinline__ float softplus_accurate(float x) {
    return log1pf(expf(x));
}

// Fused prep: u8 Z table + zero out + (thread 0) derived pair params. 8 atoms/thread.
__global__ void atoms_kernel(const float* __restrict__ Zf, float* __restrict__ out, int n,
                             const float* __restrict__ adiv, const float* __restrict__ apow,
                             const float* __restrict__ c1, const float* __restrict__ c2,
                             const float* __restrict__ c3, const float* __restrict__ c4,
                             const float* __restrict__ a1, const float* __restrict__ a2,
                             const float* __restrict__ a3, const float* __restrict__ a4) {
    int t = blockIdx.x * blockDim.x + threadIdx.x;
    if (t == 0) {
        const float KEHALF = 7.199822675975274f;
        const float NLOG2E = -1.4426950408889634f;
        float c1p = softplus_accurate(c1[0]);
        float c2p = softplus_accurate(c2[0]);
        float c3p = softplus_accurate(c3[0]);
        float c4p = softplus_accurate(c4[0]);
        float inv_csum = KEHALF / (c1p + c2p + c3p + c4p);
        g_par[0] = softplus_accurate(adiv[0]);
        g_par[1] = c1p * inv_csum;
        g_par[2] = c2p * inv_csum;
        g_par[3] = c3p * inv_csum;
        g_par[4] = c4p * inv_csum;
        g_par[5] = NLOG2E * softplus_accurate(a1[0]);
        g_par[6] = NLOG2E * softplus_accurate(a2[0]);
        g_par[7] = NLOG2E * softplus_accurate(a3[0]);
        g_par[8] = NLOG2E * softplus_accurate(a4[0]);
        g_par[9] = softplus_accurate(apow[0]);
    }
    int base = t * 8;
    if (base + 8 <= n) {
        float4 za = __ldcs(reinterpret_cast<const float4*>(Zf + base));
        float4 zb = __ldcs(reinterpret_cast<const float4*>(Zf + base + 4));
        unsigned int lo = (unsigned int)__float2int_rn(za.x)
                        | ((unsigned int)__float2int_rn(za.y) << 8)
                        | ((unsigned int)__float2int_rn(za.z) << 16)
                        | ((unsigned int)__float2int_rn(za.w) << 24);
        unsigned int hi = (unsigned int)__float2int_rn(zb.x)
                        | ((unsigned int)__float2int_rn(zb.y) << 8)
                        | ((unsigned int)__float2int_rn(zb.z) << 16)
                        | ((unsigned int)__float2int_rn(zb.w) << 24);
        *reinterpret_cast<uint2*>(g_z8 + base) = make_uint2(lo, hi);
        *reinterpret_cast<float4*>(out + base)     = make_float4(0.f, 0.f, 0.f, 0.f);
        *reinterpret_cast<float4*>(out + base + 4) = make_float4(0.f, 0.f, 0.f, 0.f);
    } else {
        for (int i = base; i < n; i++) {
            g_z8[i] = (unsigned char)__float2int_rn(Zf[i]);
            out[i] = 0.0f;
        }
    }
}

__global__ void __launch_bounds__(256) pairs_kernel(
    const float* __restrict__ rij, const float* __restrict__ cv,
    const int* __restrict__ idx_i, const int* __restrict__ idx_j,
    float* __restrict__ out, int npairs) {
    long long base = (long long)(blockIdx.x * blockDim.x + threadIdx.x) * PPT;
    if (base >= npairs) return;

    const float spadiv = g_par[0];
    const float k1 = g_par[1], k2 = g_par[2], k3 = g_par[3], k4 = g_par[4];
    const float q1 = g_par[5], q2 = g_par[6], q3 = g_par[7], q4 = g_par[8];
    const float spapow = g_par[9];

    if (base + PPT <= npairs) {
        // streaming loads: evict-first so the 0.5MB atom table keeps L1 lines
        float4 r4 = __ldcs(reinterpret_cast<const float4*>(rij + base));
        float4 c4 = __ldcs(reinterpret_cast<const float4*>(cv + base));
        int4   i4 = __ldcs(reinterpret_cast<const int4*>(idx_i + base));
        int4   j4 = __ldcs(reinterpret_cast<const int4*>(idx_j + base));
        float r[PPT] = {r4.x, r4.y, r4.z, r4.w};
        float c[PPT] = {c4.x, c4.y, c4.z, c4.w};
        int ia[PPT] = {i4.x, i4.y, i4.z, i4.w};
        int ja[PPT] = {j4.x, j4.y, j4.z, j4.w};

        // 8 u8 gathers, read-only path
        unsigned char zbi[PPT], zbj[PPT];
#pragma unroll
        for (int k = 0; k < PPT; k++) zbi[k] = __ldg(&g_z8[ia[k]]);
#pragma unroll
        for (int k = 0; k < PPT; k++) zbj[k] = __ldg(&g_z8[ja[k]]);

        float contrib[PPT];
#pragma unroll
        for (int k = 0; k < PPT; k++) {
            float Zi = (float)zbi[k];
            float Zj = (float)zbj[k];
            float zi = exp2f(spapow * __log2f(Zi));  // z = Z^sp(apow)
            float zj = exp2f(spapow * __log2f(Zj));
            float u = (zi + zj) * spadiv * r[k];     // a * r
            float f = k1 * exp2f(q1 * u)
                    + k2 * exp2f(q2 * u)
                    + k3 * exp2f(q3 * u)
                    + k4 * exp2f(q4 * u);
            contrib[k] = __fdividef(f * c[k] * Zi * Zj, r[k]);
        }
#pragma unroll
        for (int k = 0; k < PPT; k++) {
            atomicAdd(&out[ia[k]], contrib[k]);
        }
    } else {
        int cnt = (int)(npairs - base);
        for (int k = 0; k < cnt; k++) {
            float rk = rij[base + k];
            float ck = cv[base + k];
            int i = idx_i[base + k];
            int j = idx_j[base + k];
            float Zi = (float)g_z8[i];
            float Zj = (float)g_z8[j];
            float zi = exp2f(spapow * __log2f(Zi));
            float zj = exp2f(spapow * __log2f(Zj));
            float u = (zi + zj) * spadiv * rk;
            float f = k1 * exp2f(q1 * u)
                    + k2 * exp2f(q2 * u)
                    + k3 * exp2f(q3 * u)
                    + k4 * exp2f(q4 * u);
            atomicAdd(&out[i], __fdividef(f * ck * Zi * Zj, rk));
        }
    }
}

extern "C" void kernel_launch(void* const* d_in, const int* in_sizes, int n_in,
                              void* d_out, int out_size) {
    const float* Zf    = (const float*)d_in[1];
    const float* rij   = (const float*)d_in[2];
    const float* cvv   = (const float*)d_in[3];
    const int*   idx_i = (const int*)d_in[4];
    const int*   idx_j = (const int*)d_in[5];
    const float* adiv  = (const float*)d_in[6];
    const float* apow  = (const float*)d_in[7];
    const float* c1    = (const float*)d_in[8];
    const float* c2    = (const float*)d_in[9];
    const float* c3    = (const float*)d_in[10];
    const float* c4    = (const float*)d_in[11];
    const float* a1    = (const float*)d_in[12];
    const float* a2    = (const float*)d_in[13];
    const float* a3    = (const float*)d_in[14];
    const float* a4    = (const float*)d_in[15];

    int n = in_sizes[1];
    int p = in_sizes[2];
    float* out = (float*)d_out;

    int athreads = (n + 7) / 8;
    int ab = (athreads + 255) / 256;
    atoms_kernel<<<ab, 256>>>(Zf, out, n, adiv, apow, c1, c2, c3, c4, a1, a2, a3, a4);

    long long nthreads = ((long long)p + PPT - 1) / PPT;
    int pb = (int)((nthreads + 255) / 256);
    pairs_kernel<<<pb, 256>>>(rij, cvv, idx_i, idx_j, out, p);
}